// round 4
// baseline (speedup 1.0000x reference)
#include <cuda_runtime.h>

#define F_NUM 20000
#define H_NUM 40000
#define NALL  60000
#define E_NUM 640000
#define D_DIM 128
#define A_DIM 64
#define B_NUM 256
#define P_ROWS 32
#define KSPLIT 25
#define KCH (F_NUM / KSPLIT)   // 800

// s_k layout: 8 warps/block, 4 edges/warp -> 32 edges per block.
#define S_EDGES_PER_BLOCK 32
#define S_GRID (E_NUM / S_EDGES_PER_BLOCK)   // 20000
static_assert(S_GRID * S_EDGES_PER_BLOCK == E_NUM, "s_k grid must cover all edges");

typedef unsigned long long ull;

// ---- scratch (static device globals; no allocation) ----
__device__ float g_P1[F_NUM * A_DIM];
__device__ float g_P2[NALL * A_DIM];
__device__ float g_scores[E_NUM];
__device__ float g_context[F_NUM * D_DIM];
__device__ int   g_cp[E_NUM];
__device__ int   g_fci[E_NUM];
__device__ int   g_is32[2];
__device__ float g_partial[KSPLIT * B_NUM * D_DIM];

__device__ __forceinline__ float tanh_hw(float x) {
    float y;
    asm("tanh.approx.f32 %0, %1;" : "=f"(y) : "f"(x));
    return y;
}
__device__ __forceinline__ ull ffma2(ull a, ull b, ull c) {
    ull d;
    asm("fma.rn.f32x2 %0, %1, %2, %3;" : "=l"(d) : "l"(a), "l"(b), "l"(c));
    return d;
}
__device__ __forceinline__ float f2lo(ull v) { return __uint_as_float((unsigned)v); }
__device__ __forceinline__ float f2hi(ull v) { return __uint_as_float((unsigned)(v >> 32)); }
__device__ __forceinline__ ull packf2(float lo, float hi) {
    return (ull)__float_as_uint(lo) | ((ull)__float_as_uint(hi) << 32);
}

// ---------------------------------------------------------------------------
// int32/int64 index detection (probe tail as int64; int32 data yields
// high-word >= NALL).
// ---------------------------------------------------------------------------
__global__ void detect_k(const void* cp, const void* fci) {
    if (threadIdx.x != 0 || blockIdx.x != 0) return;
    const long long* p = (const long long*)cp;
    long long m = 0;
    for (int j = 1; j <= 8; ++j) {
        long long v = p[E_NUM / 2 - j];
        if (v < 0) v = (1LL << 40);
        if (v > m) m = v;
    }
    g_is32[0] = (m >= (long long)NALL) ? 1 : 0;
    const long long* q = (const long long*)fci;
    m = 0;
    for (int j = 1; j <= 8; ++j) {
        long long v = q[E_NUM / 2 - j];
        if (v < 0) v = (1LL << 40);
        if (v > m) m = v;
    }
    g_is32[1] = (m >= (long long)NALL) ? 1 : 0;
}

__global__ void convert_k(const void* cp, const void* fci) {
    int e = blockIdx.x * blockDim.x + threadIdx.x;
    if (e >= E_NUM) return;
    int is0 = g_is32[0], is1 = g_is32[1];
    g_cp[e]  = is0 ? ((const int*)cp)[e]  : (int)((const long long*)cp)[e];
    g_fci[e] = is1 ? ((const int*)fci)[e] : (int)((const long long*)fci)[e];
}

// ---------------------------------------------------------------------------
// P kernel with packed f32x2 FMA.
// P1[f][a] = sum_d feat[f][d]*W[d][a];  P2[i][a] = sum_d all[i][d]*W[128+d][a]
// 128 threads: a = tid&63, h = tid>>6 (d-half). W pairs packed in registers.
// ---------------------------------------------------------------------------
__global__ __launch_bounds__(128) void p_k(const float* __restrict__ feat,
                                           const float* __restrict__ hid,
                                           const float* __restrict__ w) {
    const int tid = threadIdx.x;
    const int a = tid & 63;
    const int h = tid >> 6;

    const int NB1 = F_NUM / P_ROWS;
    const bool reg2 = (blockIdx.x >= NB1);
    const int row0 = (reg2 ? (blockIdx.x - NB1) : blockIdx.x) * P_ROWS;
    const int wbase = reg2 ? 128 : 0;

    ull wpk[32];
#pragma unroll
    for (int j = 0; j < 32; ++j)
        wpk[j] = packf2(w[(wbase + h * 64 + 2 * j) * A_DIM + a],
                        w[(wbase + h * 64 + 2 * j + 1) * A_DIM + a]);

    __shared__ float sh[8][64];

    for (int r0 = 0; r0 < P_ROWS; r0 += 8) {
        float acc[8];
#pragma unroll
        for (int rr = 0; rr < 8; ++rr) {
            const int row = row0 + r0 + rr;
            const float* src;
            if (!reg2) {
                src = feat + (size_t)row * D_DIM;
            } else {
                src = (row < F_NUM) ? (feat + (size_t)row * D_DIM)
                                    : (hid + (size_t)(row - F_NUM) * D_DIM);
            }
            const double2* s2 = (const double2*)src;
            ull a0 = 0, a1 = 0;
#pragma unroll
            for (int j = 0; j < 16; ++j) {
                double2 v = s2[h * 16 + j];
                a0 = ffma2(__double_as_longlong(v.x), wpk[2 * j + 0], a0);
                a1 = ffma2(__double_as_longlong(v.y), wpk[2 * j + 1], a1);
            }
            acc[rr] = (f2lo(a0) + f2hi(a0)) + (f2lo(a1) + f2hi(a1));
        }
        if (h) {
#pragma unroll
            for (int rr = 0; rr < 8; ++rr) sh[rr][a] = acc[rr];
        }
        __syncthreads();
        if (!h) {
#pragma unroll
            for (int rr = 0; rr < 8; ++rr) {
                const int row = row0 + r0 + rr;
                float* dst = reg2 ? (g_P2 + (size_t)row * A_DIM)
                                  : (g_P1 + (size_t)row * A_DIM);
                dst[a] = acc[rr] + sh[rr][a];
            }
        }
        __syncthreads();
    }
}

// ---------------------------------------------------------------------------
// S kernel: 8-lane cooperative per edge -> coalesced row reads (2 lines/row).
// Lane l covers a-indices [l*4, l*4+4) and [32+l*4, 32+l*4+4).
// ---------------------------------------------------------------------------
__global__ __launch_bounds__(256) void s_k(const float* __restrict__ bias,
                                           const float* __restrict__ u,
                                           const float* __restrict__ corr) {
    const int tid = threadIdx.x;
    const int lane = tid & 31;
    const int grp = lane >> 3;
    const int l = lane & 7;
    const int warp = (blockIdx.x * 256 + tid) >> 5;
    const int e = warp * 4 + grp;

    const float4 b0 = ((const float4*)bias)[l];
    const float4 b1 = ((const float4*)bias)[l + 8];
    const float4 u0 = ((const float4*)u)[l];
    const float4 u1 = ((const float4*)u)[l + 8];

    const int c = g_cp[e];
    const int fi = g_fci[e];
    const float4* p1 = (const float4*)(g_P1 + (size_t)c * A_DIM);
    const float4* p2 = (const float4*)(g_P2 + (size_t)fi * A_DIM);
    const float4 x0 = p1[l], x1 = p1[l + 8];
    const float4 y0 = p2[l], y1 = p2[l + 8];

    float t = tanh_hw(x0.x + y0.x + b0.x) * u0.x
            + tanh_hw(x0.y + y0.y + b0.y) * u0.y
            + tanh_hw(x0.z + y0.z + b0.z) * u0.z
            + tanh_hw(x0.w + y0.w + b0.w) * u0.w
            + tanh_hw(x1.x + y1.x + b1.x) * u1.x
            + tanh_hw(x1.y + y1.y + b1.y) * u1.y
            + tanh_hw(x1.z + y1.z + b1.z) * u1.z
            + tanh_hw(x1.w + y1.w + b1.w) * u1.w;

    t += __shfl_xor_sync(0xffffffffu, t, 1);
    t += __shfl_xor_sync(0xffffffffu, t, 2);
    t += __shfl_xor_sync(0xffffffffu, t, 4);
    if (l == 0) g_scores[e] = __expf(t) * corr[e];
}

// ---------------------------------------------------------------------------
// C kernel: warp per feature segment, 4-deep manual load pipeline (MLP=4).
// ---------------------------------------------------------------------------
__device__ __forceinline__ const float4* emb_row(const float* feat, const float* hid, int fi) {
    return (const float4*)((fi < F_NUM) ? (feat + (size_t)fi * D_DIM)
                                        : (hid + (size_t)(fi - F_NUM) * D_DIM));
}

__global__ __launch_bounds__(256) void c_k(const float* __restrict__ feat,
                                           const float* __restrict__ hid) {
    const int lane = threadIdx.x & 31;
    const int f = blockIdx.x * 8 + (threadIdx.x >> 5);
    if (f >= F_NUM) return;

    int lo, hiN;
    {
        int l = 0, r = E_NUM;
        while (l < r) { int m = (l + r) >> 1; if (g_cp[m] < f) l = m + 1; else r = m; }
        lo = l;
        r = E_NUM;
        while (l < r) { int m = (l + r) >> 1; if (g_cp[m] < f + 1) l = m + 1; else r = m; }
        hiN = l;
    }

    float4 acc = make_float4(0.f, 0.f, 0.f, 0.f);
    float den = 0.f;
    int e = lo;
    for (; e + 4 <= hiN; e += 4) {
        const float s0 = g_scores[e + 0];
        const float s1 = g_scores[e + 1];
        const float s2 = g_scores[e + 2];
        const float s3 = g_scores[e + 3];
        const float4 v0 = emb_row(feat, hid, g_fci[e + 0])[lane];
        const float4 v1 = emb_row(feat, hid, g_fci[e + 1])[lane];
        const float4 v2 = emb_row(feat, hid, g_fci[e + 2])[lane];
        const float4 v3 = emb_row(feat, hid, g_fci[e + 3])[lane];
        acc.x += s0 * v0.x + s1 * v1.x + s2 * v2.x + s3 * v3.x;
        acc.y += s0 * v0.y + s1 * v1.y + s2 * v2.y + s3 * v3.y;
        acc.z += s0 * v0.z + s1 * v1.z + s2 * v2.z + s3 * v3.z;
        acc.w += s0 * v0.w + s1 * v1.w + s2 * v2.w + s3 * v3.w;
        den += (s0 + s1) + (s2 + s3);
    }
    for (; e < hiN; ++e) {
        const float s = g_scores[e];
        const float4 v = emb_row(feat, hid, g_fci[e])[lane];
        acc.x += s * v.x; acc.y += s * v.y; acc.z += s * v.z; acc.w += s * v.w;
        den += s;
    }
    const float inv = (den != 0.f) ? (1.f / den) : 0.f;
    float4 o = make_float4(acc.x * inv, acc.y * inv, acc.z * inv, acc.w * inv);
    ((float4*)(g_context + (size_t)f * D_DIM))[lane] = o;
}

// ---------------------------------------------------------------------------
// G kernels: out[256,128] = values[256,F] @ context[F,128].
// 32 b-rows per block (halves context L2 traffic), packed f32x2 FMA.
// ---------------------------------------------------------------------------
__global__ __launch_bounds__(256) void g1_k(const float* __restrict__ values) {
    const int tid = threadIdx.x;
    const int d = tid & 127;
    const int bh = tid >> 7;
    const int b0 = blockIdx.x * 32 + bh * 16;
    const int k0 = blockIdx.y * KCH;

    ull acc[16];
#pragma unroll
    for (int i = 0; i < 16; ++i) acc[i] = 0;

    for (int k = k0; k < k0 + KCH; k += 4) {
        const float c0 = g_context[(size_t)(k + 0) * D_DIM + d];
        const float c1 = g_context[(size_t)(k + 1) * D_DIM + d];
        const float c2 = g_context[(size_t)(k + 2) * D_DIM + d];
        const float c3 = g_context[(size_t)(k + 3) * D_DIM + d];
        const ull c01 = packf2(c0, c1);
        const ull c23 = packf2(c2, c3);
#pragma unroll
        for (int i = 0; i < 16; ++i) {
            const double2 v = *(const double2*)(values + (size_t)(b0 + i) * F_NUM + k);
            acc[i] = ffma2(__double_as_longlong(v.x), c01, acc[i]);
            acc[i] = ffma2(__double_as_longlong(v.y), c23, acc[i]);
        }
    }
    float* part = g_partial + (size_t)blockIdx.y * (B_NUM * D_DIM);
#pragma unroll
    for (int i = 0; i < 16; ++i)
        part[(size_t)(b0 + i) * D_DIM + d] = f2lo(acc[i]) + f2hi(acc[i]);
}

__global__ __launch_bounds__(256) void g2_k(float* __restrict__ out) {
    const int i = blockIdx.x * blockDim.x + threadIdx.x;
    if (i >= B_NUM * D_DIM) return;
    float s = 0.f;
#pragma unroll
    for (int j = 0; j < KSPLIT; ++j) s += g_partial[(size_t)j * (B_NUM * D_DIM) + i];
    out[i] = s;
}

// ---------------------------------------------------------------------------
extern "C" void kernel_launch(void* const* d_in, const int* in_sizes, int n_in,
                              void* d_out, int out_size) {
    const float* values = (const float*)d_in[0];
    const float* feat   = (const float*)d_in[1];
    const float* hid    = (const float*)d_in[2];
    const float* w      = (const float*)d_in[3];
    const float* bias   = (const float*)d_in[4];
    const float* u      = (const float*)d_in[5];
    const float* corr   = (const float*)d_in[6];
    const void*  cp     = d_in[7];
    const void*  fci    = d_in[8];
    float* out = (float*)d_out;

    detect_k<<<1, 32>>>(cp, fci);
    convert_k<<<(E_NUM + 255) / 256, 256>>>(cp, fci);
    p_k<<<(F_NUM + NALL) / P_ROWS, 128>>>(feat, hid, w);
    s_k<<<S_GRID, 256>>>(bias, u, corr);
    c_k<<<F_NUM / 8, 256>>>(feat, hid);
    g1_k<<<dim3(8, KSPLIT), 256>>>(values);
    g2_k<<<(B_NUM * D_DIM + 255) / 256, 256>>>(out);
}

// round 5
// speedup vs baseline: 1.6084x; 1.6084x over previous
#include <cuda_runtime.h>

#define F_NUM 20000
#define H_NUM 40000
#define NALL  60000
#define E_NUM 640000
#define D_DIM 128
#define A_DIM 64
#define B_NUM 256
#define P_ROWS 32
#define KSPLIT 50
#define KCH (F_NUM / KSPLIT)   // 400

// s_k layout: 8 warps/block, 4 edges/warp -> 32 edges per block.
#define S_EDGES_PER_BLOCK 32
#define S_GRID (E_NUM / S_EDGES_PER_BLOCK)   // 20000
static_assert(S_GRID * S_EDGES_PER_BLOCK == E_NUM, "s_k grid must cover all edges");
static_assert(KSPLIT * KCH == F_NUM, "split-K must tile F exactly");

// ---- scratch (static device globals; no allocation) ----
__device__ float g_P1[F_NUM * A_DIM];
__device__ float g_P2[NALL * A_DIM];
__device__ float g_scores[E_NUM];
__device__ float g_context[F_NUM * D_DIM];
__device__ int   g_cp[E_NUM];
__device__ int   g_fci[E_NUM];
__device__ int   g_is32[2];
__device__ int   g_segstart[F_NUM + 1];
__device__ float g_partial[KSPLIT * B_NUM * D_DIM];

__device__ __forceinline__ float tanh_hw(float x) {
    float y;
    asm("tanh.approx.f32 %0, %1;" : "=f"(y) : "f"(x));
    return y;
}

// ---------------------------------------------------------------------------
// int32/int64 index detection (probe tail as int64; int32 data yields
// high-word >= NALL).
// ---------------------------------------------------------------------------
__global__ void detect_k(const void* cp, const void* fci) {
    if (threadIdx.x != 0 || blockIdx.x != 0) return;
    const long long* p = (const long long*)cp;
    long long m = 0;
    for (int j = 1; j <= 8; ++j) {
        long long v = p[E_NUM / 2 - j];
        if (v < 0) v = (1LL << 40);
        if (v > m) m = v;
    }
    g_is32[0] = (m >= (long long)NALL) ? 1 : 0;
    const long long* q = (const long long*)fci;
    m = 0;
    for (int j = 1; j <= 8; ++j) {
        long long v = q[E_NUM / 2 - j];
        if (v < 0) v = (1LL << 40);
        if (v > m) m = v;
    }
    g_is32[1] = (m >= (long long)NALL) ? 1 : 0;
}

__global__ void convert_k(const void* cp, const void* fci) {
    int e = blockIdx.x * blockDim.x + threadIdx.x;
    if (e >= E_NUM) return;
    int is0 = g_is32[0], is1 = g_is32[1];
    g_cp[e]  = is0 ? ((const int*)cp)[e]  : (int)((const long long*)cp)[e];
    g_fci[e] = is1 ? ((const int*)fci)[e] : (int)((const long long*)fci)[e];
}

// ---------------------------------------------------------------------------
// seg_k: segment offsets from sorted cp. segstart[f] = first e with cp[e] >= f.
// Each boundary written by exactly one thread -> deterministic.
// ---------------------------------------------------------------------------
__global__ void seg_k() {
    int e = blockIdx.x * blockDim.x + threadIdx.x;
    if (e >= E_NUM) return;
    const int c = g_cp[e];
    const int prev = (e == 0) ? -1 : g_cp[e - 1];
    for (int f = prev + 1; f <= c; ++f) g_segstart[f] = e;
    if (e == E_NUM - 1)
        for (int f = c + 1; f <= F_NUM; ++f) g_segstart[f] = E_NUM;
}

// ---------------------------------------------------------------------------
// P kernel: P1[f][a] = sum_d feat[f][d]*W[d][a] (W rows 0..127)
//           P2[i][a] = sum_d all[i][d]*W[128+d][a] (W rows 128..255)
// 128 threads: a = tid&63, h = tid>>6 (d-half). 64 W floats per thread in
// registers; 8 rows per barrier pair.
// ---------------------------------------------------------------------------
__global__ __launch_bounds__(128) void p_k(const float* __restrict__ feat,
                                           const float* __restrict__ hid,
                                           const float* __restrict__ w) {
    const int tid = threadIdx.x;
    const int a = tid & 63;
    const int h = tid >> 6;

    const int NB1 = F_NUM / P_ROWS;
    const bool reg2 = (blockIdx.x >= NB1);
    const int row0 = (reg2 ? (blockIdx.x - NB1) : blockIdx.x) * P_ROWS;
    const int wbase = reg2 ? 128 : 0;

    float wr[64];
#pragma unroll
    for (int j = 0; j < 64; ++j)
        wr[j] = w[(wbase + h * 64 + j) * A_DIM + a];

    __shared__ float sh[8][64];

    for (int r0 = 0; r0 < P_ROWS; r0 += 8) {
        float acc[8];
#pragma unroll
        for (int rr = 0; rr < 8; ++rr) {
            const int row = row0 + r0 + rr;
            const float* src;
            if (!reg2) {
                src = feat + (size_t)row * D_DIM;
            } else {
                src = (row < F_NUM) ? (feat + (size_t)row * D_DIM)
                                    : (hid + (size_t)(row - F_NUM) * D_DIM);
            }
            const float4* s4 = (const float4*)src;
            float a0 = 0.f, a1 = 0.f, a2 = 0.f, a3 = 0.f;
#pragma unroll
            for (int j = 0; j < 16; ++j) {
                float4 v = s4[h * 16 + j];
                a0 += v.x * wr[4 * j + 0];
                a1 += v.y * wr[4 * j + 1];
                a2 += v.z * wr[4 * j + 2];
                a3 += v.w * wr[4 * j + 3];
            }
            acc[rr] = (a0 + a1) + (a2 + a3);
        }
        if (h) {
#pragma unroll
            for (int rr = 0; rr < 8; ++rr) sh[rr][a] = acc[rr];
        }
        __syncthreads();
        if (!h) {
#pragma unroll
            for (int rr = 0; rr < 8; ++rr) {
                const int row = row0 + r0 + rr;
                float* dst = reg2 ? (g_P2 + (size_t)row * A_DIM)
                                  : (g_P1 + (size_t)row * A_DIM);
                dst[a] = acc[rr] + sh[rr][a];
            }
        }
        __syncthreads();
    }
}

// ---------------------------------------------------------------------------
// S kernel: 8-lane cooperative per edge -> coalesced row reads (2 lines/row).
// ---------------------------------------------------------------------------
__global__ __launch_bounds__(256) void s_k(const float* __restrict__ bias,
                                           const float* __restrict__ u,
                                           const float* __restrict__ corr) {
    const int tid = threadIdx.x;
    const int lane = tid & 31;
    const int grp = lane >> 3;
    const int l = lane & 7;
    const int warp = (blockIdx.x * 256 + tid) >> 5;
    const int e = warp * 4 + grp;

    const float4 b0 = ((const float4*)bias)[l];
    const float4 b1 = ((const float4*)bias)[l + 8];
    const float4 u0 = ((const float4*)u)[l];
    const float4 u1 = ((const float4*)u)[l + 8];

    const int c = g_cp[e];
    const int fi = g_fci[e];
    const float4* p1 = (const float4*)(g_P1 + (size_t)c * A_DIM);
    const float4* p2 = (const float4*)(g_P2 + (size_t)fi * A_DIM);
    const float4 x0 = p1[l], x1 = p1[l + 8];
    const float4 y0 = p2[l], y1 = p2[l + 8];

    float t = tanh_hw(x0.x + y0.x + b0.x) * u0.x
            + tanh_hw(x0.y + y0.y + b0.y) * u0.y
            + tanh_hw(x0.z + y0.z + b0.z) * u0.z
            + tanh_hw(x0.w + y0.w + b0.w) * u0.w
            + tanh_hw(x1.x + y1.x + b1.x) * u1.x
            + tanh_hw(x1.y + y1.y + b1.y) * u1.y
            + tanh_hw(x1.z + y1.z + b1.z) * u1.z
            + tanh_hw(x1.w + y1.w + b1.w) * u1.w;

    t += __shfl_xor_sync(0xffffffffu, t, 1);
    t += __shfl_xor_sync(0xffffffffu, t, 2);
    t += __shfl_xor_sync(0xffffffffu, t, 4);
    if (l == 0) g_scores[e] = __expf(t) * corr[e];
}

// ---------------------------------------------------------------------------
// C kernel: warp per feature segment, precomputed bounds, 4-deep pipeline.
// ---------------------------------------------------------------------------
__device__ __forceinline__ const float4* emb_row(const float* feat, const float* hid, int fi) {
    return (const float4*)((fi < F_NUM) ? (feat + (size_t)fi * D_DIM)
                                        : (hid + (size_t)(fi - F_NUM) * D_DIM));
}

__global__ __launch_bounds__(256) void c_k(const float* __restrict__ feat,
                                           const float* __restrict__ hid) {
    const int lane = threadIdx.x & 31;
    const int f = blockIdx.x * 8 + (threadIdx.x >> 5);
    if (f >= F_NUM) return;

    const int lo = g_segstart[f];
    const int hiN = g_segstart[f + 1];

    float4 acc = make_float4(0.f, 0.f, 0.f, 0.f);
    float den = 0.f;
    int e = lo;
    for (; e + 4 <= hiN; e += 4) {
        const float s0 = g_scores[e + 0];
        const float s1 = g_scores[e + 1];
        const float s2 = g_scores[e + 2];
        const float s3 = g_scores[e + 3];
        const float4 v0 = emb_row(feat, hid, g_fci[e + 0])[lane];
        const float4 v1 = emb_row(feat, hid, g_fci[e + 1])[lane];
        const float4 v2 = emb_row(feat, hid, g_fci[e + 2])[lane];
        const float4 v3 = emb_row(feat, hid, g_fci[e + 3])[lane];
        acc.x += s0 * v0.x + s1 * v1.x + s2 * v2.x + s3 * v3.x;
        acc.y += s0 * v0.y + s1 * v1.y + s2 * v2.y + s3 * v3.y;
        acc.z += s0 * v0.z + s1 * v1.z + s2 * v2.z + s3 * v3.z;
        acc.w += s0 * v0.w + s1 * v1.w + s2 * v2.w + s3 * v3.w;
        den += (s0 + s1) + (s2 + s3);
    }
    for (; e < hiN; ++e) {
        const float s = g_scores[e];
        const float4 v = emb_row(feat, hid, g_fci[e])[lane];
        acc.x += s * v.x; acc.y += s * v.y; acc.z += s * v.z; acc.w += s * v.w;
        den += s;
    }
    const float inv = (den != 0.f) ? (1.f / den) : 0.f;
    float4 o = make_float4(acc.x * inv, acc.y * inv, acc.z * inv, acc.w * inv);
    ((float4*)(g_context + (size_t)f * D_DIM))[lane] = o;
}

// ---------------------------------------------------------------------------
// G kernels: out[256,128] = values[256,F] @ context[F,128].
// Split-K (50) deterministic partials + reduction. Scalar FFMA.
// ---------------------------------------------------------------------------
__global__ __launch_bounds__(256) void g1_k(const float* __restrict__ values) {
    const int tid = threadIdx.x;
    const int d = tid & 127;
    const int bh = tid >> 7;
    const int b0 = blockIdx.x * 16 + bh * 8;
    const int k0 = blockIdx.y * KCH;

    float acc[8];
#pragma unroll
    for (int i = 0; i < 8; ++i) acc[i] = 0.f;

    for (int k = k0; k < k0 + KCH; k += 4) {
        const float c0 = g_context[(size_t)(k + 0) * D_DIM + d];
        const float c1 = g_context[(size_t)(k + 1) * D_DIM + d];
        const float c2 = g_context[(size_t)(k + 2) * D_DIM + d];
        const float c3 = g_context[(size_t)(k + 3) * D_DIM + d];
#pragma unroll
        for (int i = 0; i < 8; ++i) {
            const float4 v = *(const float4*)(values + (size_t)(b0 + i) * F_NUM + k);
            acc[i] += v.x * c0 + v.y * c1 + v.z * c2 + v.w * c3;
        }
    }
    float* part = g_partial + (size_t)blockIdx.y * (B_NUM * D_DIM);
#pragma unroll
    for (int i = 0; i < 8; ++i) part[(size_t)(b0 + i) * D_DIM + d] = acc[i];
}

__global__ __launch_bounds__(256) void g2_k(float* __restrict__ out) {
    const int i = blockIdx.x * blockDim.x + threadIdx.x;
    if (i >= B_NUM * D_DIM) return;
    float s = 0.f;
#pragma unroll
    for (int j = 0; j < KSPLIT; ++j) s += g_partial[(size_t)j * (B_NUM * D_DIM) + i];
    out[i] = s;
}

// ---------------------------------------------------------------------------
extern "C" void kernel_launch(void* const* d_in, const int* in_sizes, int n_in,
                              void* d_out, int out_size) {
    const float* values = (const float*)d_in[0];
    const float* feat   = (const float*)d_in[1];
    const float* hid    = (const float*)d_in[2];
    const float* w      = (const float*)d_in[3];
    const float* bias   = (const float*)d_in[4];
    const float* u      = (const float*)d_in[5];
    const float* corr   = (const float*)d_in[6];
    const void*  cp     = d_in[7];
    const void*  fci    = d_in[8];
    float* out = (float*)d_out;

    detect_k<<<1, 32>>>(cp, fci);
    convert_k<<<(E_NUM + 255) / 256, 256>>>(cp, fci);
    seg_k<<<(E_NUM + 255) / 256, 256>>>();
    p_k<<<(F_NUM + NALL) / P_ROWS, 128>>>(feat, hid, w);
    s_k<<<S_GRID, 256>>>(bias, u, corr);
    c_k<<<F_NUM / 8, 256>>>(feat, hid);
    g1_k<<<dim3(16, KSPLIT), 256>>>(values);
    g2_k<<<(B_NUM * D_DIM + 255) / 256, 256>>>(out);
}

// round 6
// speedup vs baseline: 1.6225x; 1.0088x over previous
#include <cuda_runtime.h>

#define F_NUM 20000
#define H_NUM 40000
#define NALL  60000
#define E_NUM 640000
#define D_DIM 128
#define A_DIM 64
#define B_NUM 256
#define KSPLIT 100
#define KCH (F_NUM / KSPLIT)   // 200

// p_k tiling: 64 rows per block, processed in 8-row staged batches.
#define PT_ROWS 64
#define PB1 ((F_NUM + PT_ROWS - 1) / PT_ROWS)   // 313
#define PB2 ((NALL + PT_ROWS - 1) / PT_ROWS)    // 938

// s_k layout: 8 warps/block, 4 edges/warp -> 32 edges per block.
#define S_EDGES_PER_BLOCK 32
#define S_GRID (E_NUM / S_EDGES_PER_BLOCK)   // 20000
static_assert(S_GRID * S_EDGES_PER_BLOCK == E_NUM, "s_k grid must cover all edges");
static_assert(KSPLIT * KCH == F_NUM, "split-K must tile F exactly");

// ---- scratch (static device globals; no allocation) ----
__device__ float g_P1[F_NUM * A_DIM];
__device__ float g_P2[NALL * A_DIM];
__device__ float g_scores[E_NUM];
__device__ float g_context[F_NUM * D_DIM];
__device__ int   g_cp[E_NUM];
__device__ int   g_fci[E_NUM];
__device__ int   g_is32[2];
__device__ int   g_segstart[F_NUM + 1];
__device__ float g_partial[KSPLIT * B_NUM * D_DIM];

__device__ __forceinline__ float tanh_hw(float x) {
    float y;
    asm("tanh.approx.f32 %0, %1;" : "=f"(y) : "f"(x));
    return y;
}

// ---------------------------------------------------------------------------
// int32/int64 index detection (probe tail as int64; int32 data yields
// high-word >= NALL).
// ---------------------------------------------------------------------------
__global__ void detect_k(const void* cp, const void* fci) {
    if (threadIdx.x != 0 || blockIdx.x != 0) return;
    const long long* p = (const long long*)cp;
    long long m = 0;
    for (int j = 1; j <= 8; ++j) {
        long long v = p[E_NUM / 2 - j];
        if (v < 0) v = (1LL << 40);
        if (v > m) m = v;
    }
    g_is32[0] = (m >= (long long)NALL) ? 1 : 0;
    const long long* q = (const long long*)fci;
    m = 0;
    for (int j = 1; j <= 8; ++j) {
        long long v = q[E_NUM / 2 - j];
        if (v < 0) v = (1LL << 40);
        if (v > m) m = v;
    }
    g_is32[1] = (m >= (long long)NALL) ? 1 : 0;
}

__global__ void convert_k(const void* cp, const void* fci) {
    int e = blockIdx.x * blockDim.x + threadIdx.x;
    if (e >= E_NUM) return;
    int is0 = g_is32[0], is1 = g_is32[1];
    g_cp[e]  = is0 ? ((const int*)cp)[e]  : (int)((const long long*)cp)[e];
    g_fci[e] = is1 ? ((const int*)fci)[e] : (int)((const long long*)fci)[e];
}

// ---------------------------------------------------------------------------
// seg_k: segment offsets from sorted cp. segstart[f] = first e with cp[e] >= f.
// ---------------------------------------------------------------------------
__global__ void seg_k() {
    int e = blockIdx.x * blockDim.x + threadIdx.x;
    if (e >= E_NUM) return;
    const int c = g_cp[e];
    const int prev = (e == 0) ? -1 : g_cp[e - 1];
    for (int f = prev + 1; f <= c; ++f) g_segstart[f] = e;
    if (e == E_NUM - 1)
        for (int f = c + 1; f <= F_NUM; ++f) g_segstart[f] = E_NUM;
}

// ---------------------------------------------------------------------------
// P kernel v2: smem-staged rows, 4-way d-split, 256 threads.
// a = tid&63 (output col), h = tid>>6 (d-quarter, 32 d each).
// Batch of 8 rows staged coalescedly into smem; broadcast LDS reads;
// quarter-partials reduced through smem by the h==0 group.
// ---------------------------------------------------------------------------
__global__ __launch_bounds__(256) void p_k(const float* __restrict__ feat,
                                           const float* __restrict__ hid,
                                           const float* __restrict__ w) {
    const int tid = threadIdx.x;
    const int a = tid & 63;
    const int h = tid >> 6;

    const bool reg2 = (blockIdx.x >= PB1);
    const int row0 = (reg2 ? (blockIdx.x - PB1) : blockIdx.x) * PT_ROWS;
    const int limit = reg2 ? NALL : F_NUM;
    const int wbase = reg2 ? 128 : 0;

    float wr[32];
#pragma unroll
    for (int j = 0; j < 32; ++j)
        wr[j] = w[(wbase + h * 32 + j) * A_DIM + a];

    __shared__ float4 stage[8][32];      // 8 rows x 128 floats
    __shared__ float red[3][8][64];      // partials from h = 1..3

    for (int b = 0; b < PT_ROWS / 8; ++b) {
        // stage 8 rows (one warp per row, fully coalesced)
        {
            const int rr = tid >> 5;
            const int c4 = tid & 31;
            const int row = row0 + b * 8 + rr;
            float4 v = make_float4(0.f, 0.f, 0.f, 0.f);
            if (row < limit) {
                const float* src;
                if (!reg2) src = feat + (size_t)row * D_DIM;
                else       src = (row < F_NUM) ? (feat + (size_t)row * D_DIM)
                                               : (hid + (size_t)(row - F_NUM) * D_DIM);
                v = ((const float4*)src)[c4];
            }
            stage[rr][c4] = v;
        }
        __syncthreads();

        float part[8];
#pragma unroll
        for (int rr = 0; rr < 8; ++rr) {
            const float4* s4 = &stage[rr][h * 8];
            float a0 = 0.f, a1 = 0.f, a2 = 0.f, a3 = 0.f;
#pragma unroll
            for (int j = 0; j < 8; ++j) {
                const float4 v = s4[j];
                a0 += v.x * wr[4 * j + 0];
                a1 += v.y * wr[4 * j + 1];
                a2 += v.z * wr[4 * j + 2];
                a3 += v.w * wr[4 * j + 3];
            }
            part[rr] = (a0 + a1) + (a2 + a3);
        }
        if (h) {
#pragma unroll
            for (int rr = 0; rr < 8; ++rr) red[h - 1][rr][a] = part[rr];
        }
        __syncthreads();
        if (!h) {
#pragma unroll
            for (int rr = 0; rr < 8; ++rr) {
                const int row = row0 + b * 8 + rr;
                if (row < limit) {
                    const float o = (part[rr] + red[0][rr][a])
                                  + (red[1][rr][a] + red[2][rr][a]);
                    float* dst = reg2 ? (g_P2 + (size_t)row * A_DIM)
                                      : (g_P1 + (size_t)row * A_DIM);
                    dst[a] = o;
                }
            }
        }
        __syncthreads();
    }
}

// ---------------------------------------------------------------------------
// S kernel: 8-lane cooperative per edge -> coalesced row reads (2 lines/row).
// ---------------------------------------------------------------------------
__global__ __launch_bounds__(256) void s_k(const float* __restrict__ bias,
                                           const float* __restrict__ u,
                                           const float* __restrict__ corr) {
    const int tid = threadIdx.x;
    const int lane = tid & 31;
    const int grp = lane >> 3;
    const int l = lane & 7;
    const int warp = (blockIdx.x * 256 + tid) >> 5;
    const int e = warp * 4 + grp;

    const float4 b0 = ((const float4*)bias)[l];
    const float4 b1 = ((const float4*)bias)[l + 8];
    const float4 u0 = ((const float4*)u)[l];
    const float4 u1 = ((const float4*)u)[l + 8];

    const int c = g_cp[e];
    const int fi = g_fci[e];
    const float4* p1 = (const float4*)(g_P1 + (size_t)c * A_DIM);
    const float4* p2 = (const float4*)(g_P2 + (size_t)fi * A_DIM);
    const float4 x0 = p1[l], x1 = p1[l + 8];
    const float4 y0 = p2[l], y1 = p2[l + 8];

    float t = tanh_hw(x0.x + y0.x + b0.x) * u0.x
            + tanh_hw(x0.y + y0.y + b0.y) * u0.y
            + tanh_hw(x0.z + y0.z + b0.z) * u0.z
            + tanh_hw(x0.w + y0.w + b0.w) * u0.w
            + tanh_hw(x1.x + y1.x + b1.x) * u1.x
            + tanh_hw(x1.y + y1.y + b1.y) * u1.y
            + tanh_hw(x1.z + y1.z + b1.z) * u1.z
            + tanh_hw(x1.w + y1.w + b1.w) * u1.w;

    t += __shfl_xor_sync(0xffffffffu, t, 1);
    t += __shfl_xor_sync(0xffffffffu, t, 2);
    t += __shfl_xor_sync(0xffffffffu, t, 4);
    if (l == 0) g_scores[e] = __expf(t) * corr[e];
}

// ---------------------------------------------------------------------------
// C kernel: warp per feature segment, precomputed bounds, 4-deep pipeline.
// ---------------------------------------------------------------------------
__device__ __forceinline__ const float4* emb_row(const float* feat, const float* hid, int fi) {
    return (const float4*)((fi < F_NUM) ? (feat + (size_t)fi * D_DIM)
                                        : (hid + (size_t)(fi - F_NUM) * D_DIM));
}

__global__ __launch_bounds__(256) void c_k(const float* __restrict__ feat,
                                           const float* __restrict__ hid) {
    const int lane = threadIdx.x & 31;
    const int f = blockIdx.x * 8 + (threadIdx.x >> 5);
    if (f >= F_NUM) return;

    const int lo = g_segstart[f];
    const int hiN = g_segstart[f + 1];

    float4 acc = make_float4(0.f, 0.f, 0.f, 0.f);
    float den = 0.f;
    int e = lo;
    for (; e + 4 <= hiN; e += 4) {
        const float s0 = g_scores[e + 0];
        const float s1 = g_scores[e + 1];
        const float s2 = g_scores[e + 2];
        const float s3 = g_scores[e + 3];
        const float4 v0 = emb_row(feat, hid, g_fci[e + 0])[lane];
        const float4 v1 = emb_row(feat, hid, g_fci[e + 1])[lane];
        const float4 v2 = emb_row(feat, hid, g_fci[e + 2])[lane];
        const float4 v3 = emb_row(feat, hid, g_fci[e + 3])[lane];
        acc.x += s0 * v0.x + s1 * v1.x + s2 * v2.x + s3 * v3.x;
        acc.y += s0 * v0.y + s1 * v1.y + s2 * v2.y + s3 * v3.y;
        acc.z += s0 * v0.z + s1 * v1.z + s2 * v2.z + s3 * v3.z;
        acc.w += s0 * v0.w + s1 * v1.w + s2 * v2.w + s3 * v3.w;
        den += (s0 + s1) + (s2 + s3);
    }
    for (; e < hiN; ++e) {
        const float s = g_scores[e];
        const float4 v = emb_row(feat, hid, g_fci[e])[lane];
        acc.x += s * v.x; acc.y += s * v.y; acc.z += s * v.z; acc.w += s * v.w;
        den += s;
    }
    const float inv = (den != 0.f) ? (1.f / den) : 0.f;
    float4 o = make_float4(acc.x * inv, acc.y * inv, acc.z * inv, acc.w * inv);
    ((float4*)(g_context + (size_t)f * D_DIM))[lane] = o;
}

// ---------------------------------------------------------------------------
// G kernels: out[256,128] = values[256,F] @ context[F,128].
// 32 b-rows per block (halves context L2 traffic), split-K=100.
// ---------------------------------------------------------------------------
__global__ __launch_bounds__(256) void g1_k(const float* __restrict__ values) {
    const int tid = threadIdx.x;
    const int d = tid & 127;
    const int bh = tid >> 7;
    const int b0 = blockIdx.x * 32 + bh * 16;
    const int k0 = blockIdx.y * KCH;

    float acc[16];
#pragma unroll
    for (int i = 0; i < 16; ++i) acc[i] = 0.f;

    for (int k = k0; k < k0 + KCH; k += 4) {
        const float c0 = g_context[(size_t)(k + 0) * D_DIM + d];
        const float c1 = g_context[(size_t)(k + 1) * D_DIM + d];
        const float c2 = g_context[(size_t)(k + 2) * D_DIM + d];
        const float c3 = g_context[(size_t)(k + 3) * D_DIM + d];
#pragma unroll
        for (int i = 0; i < 16; ++i) {
            const float4 v = *(const float4*)(values + (size_t)(b0 + i) * F_NUM + k);
            acc[i] += v.x * c0 + v.y * c1 + v.z * c2 + v.w * c3;
        }
    }
    float* part = g_partial + (size_t)blockIdx.y * (B_NUM * D_DIM);
#pragma unroll
    for (int i = 0; i < 16; ++i) part[(size_t)(b0 + i) * D_DIM + d] = acc[i];
}

__global__ __launch_bounds__(256) void g2_k(float* __restrict__ out) {
    const int i = blockIdx.x * blockDim.x + threadIdx.x;
    if (i >= B_NUM * D_DIM) return;
    float s = 0.f;
#pragma unroll
    for (int j = 0; j < KSPLIT; ++j) s += g_partial[(size_t)j * (B_NUM * D_DIM) + i];
    out[i] = s;
}

// ---------------------------------------------------------------------------
extern "C" void kernel_launch(void* const* d_in, const int* in_sizes, int n_in,
                              void* d_out, int out_size) {
    const float* values = (const float*)d_in[0];
    const float* feat   = (const float*)d_in[1];
    const float* hid    = (const float*)d_in[2];
    const float* w      = (const float*)d_in[3];
    const float* bias   = (const float*)d_in[4];
    const float* u      = (const float*)d_in[5];
    const float* corr   = (const float*)d_in[6];
    const void*  cp     = d_in[7];
    const void*  fci    = d_in[8];
    float* out = (float*)d_out;

    detect_k<<<1, 32>>>(cp, fci);
    convert_k<<<(E_NUM + 255) / 256, 256>>>(cp, fci);
    seg_k<<<(E_NUM + 255) / 256, 256>>>();
    p_k<<<PB1 + PB2, 256>>>(feat, hid, w);
    s_k<<<S_GRID, 256>>>(bias, u, corr);
    c_k<<<F_NUM / 8, 256>>>(feat, hid);
    g1_k<<<dim3(8, KSPLIT), 256>>>(values);
    g2_k<<<(B_NUM * D_DIM + 255) / 256, 256>>>(out);
}